// round 1
// baseline (speedup 1.0000x reference)
#include <cuda_runtime.h>
#include <cuda_bf16.h>
#include <math_constants.h>
#include <cstdint>

// Problem constants
#define T_SEQ 4096
#define C_EMB 2048
#define HQ 16
#define HKV 4
#define HD 128
#define HD2 64

// Scratch (device globals; allocation in kernel_launch is forbidden)
__device__ float g_q[T_SEQ * HQ * HD];     // 32 MB
__device__ float g_k[T_SEQ * HKV * HD];    // 8 MB
__device__ float g_v[T_SEQ * HKV * HD];    // 8 MB
__device__ float g_att[T_SEQ * HQ * HD];   // 32 MB

// ---------------------------------------------------------------------------
// SGEMM: C[M,N] = A[M,K] @ B[K,N], row-major, all dims multiples of tile sizes
// BM=128, BN=128, BK=16, 256 threads, 8x8 per thread
// ---------------------------------------------------------------------------
#define BM 128
#define BN 128
#define BKK 16

__global__ __launch_bounds__(256) void sgemm_kernel(
    const float* __restrict__ A, const float* __restrict__ B,
    float* __restrict__ C, int M, int N, int K)
{
    __shared__ float As[BKK][BM];   // transposed A tile
    __shared__ float Bs[BKK][BN];

    int tid = threadIdx.x;
    int bx = blockIdx.x, by = blockIdx.y;
    int tx = tid & 15, ty = tid >> 4;

    const float* Ablk = A + (size_t)by * BM * K;
    const float* Bblk = B + (size_t)bx * BN;

    float acc[8][8];
#pragma unroll
    for (int i = 0; i < 8; i++)
#pragma unroll
        for (int j = 0; j < 8; j++) acc[i][j] = 0.f;

    for (int k0 = 0; k0 < K; k0 += BKK) {
        // Load A tile (128 x 16 floats = 512 float4), store transposed
#pragma unroll
        for (int i = 0; i < 2; i++) {
            int e = tid + i * 256;
            int r  = e >> 2;       // row within tile 0..127
            int c4 = e & 3;        // float4 within row (16 floats = 4 float4)
            float4 v = *(const float4*)(Ablk + (size_t)r * K + k0 + c4 * 4);
            As[c4 * 4 + 0][r] = v.x;
            As[c4 * 4 + 1][r] = v.y;
            As[c4 * 4 + 2][r] = v.z;
            As[c4 * 4 + 3][r] = v.w;
        }
        // Load B tile (16 x 128 floats = 512 float4)
#pragma unroll
        for (int i = 0; i < 2; i++) {
            int e = tid + i * 256;
            int r  = e >> 5;       // 0..15
            int c4 = e & 31;       // 0..31
            float4 v = *(const float4*)(Bblk + (size_t)(k0 + r) * N + c4 * 4);
            *(float4*)&Bs[r][c4 * 4] = v;
        }
        __syncthreads();

#pragma unroll
        for (int kk = 0; kk < BKK; kk++) {
            float ra[8], rb[8];
#pragma unroll
            for (int i = 0; i < 4; i++) {
                float4 v = *(const float4*)&As[kk][ty * 8 + i * 4];
                ra[i*4] = v.x; ra[i*4+1] = v.y; ra[i*4+2] = v.z; ra[i*4+3] = v.w;
                if (i == 1) break;
            }
            {
                float4 v0 = *(const float4*)&As[kk][ty * 8];
                float4 v1 = *(const float4*)&As[kk][ty * 8 + 4];
                ra[0]=v0.x; ra[1]=v0.y; ra[2]=v0.z; ra[3]=v0.w;
                ra[4]=v1.x; ra[5]=v1.y; ra[6]=v1.z; ra[7]=v1.w;
            }
            {
                float4 v0 = *(const float4*)&Bs[kk][tx * 8];
                float4 v1 = *(const float4*)&Bs[kk][tx * 8 + 4];
                rb[0]=v0.x; rb[1]=v0.y; rb[2]=v0.z; rb[3]=v0.w;
                rb[4]=v1.x; rb[5]=v1.y; rb[6]=v1.z; rb[7]=v1.w;
            }
#pragma unroll
            for (int i = 0; i < 8; i++)
#pragma unroll
                for (int j = 0; j < 8; j++)
                    acc[i][j] += ra[i] * rb[j];
        }
        __syncthreads();
    }

#pragma unroll
    for (int i = 0; i < 8; i++) {
        int r = by * BM + ty * 8 + i;
        float* Crow = C + (size_t)r * N + bx * BN + tx * 8;
        float4 v0 = {acc[i][0], acc[i][1], acc[i][2], acc[i][3]};
        float4 v1 = {acc[i][4], acc[i][5], acc[i][6], acc[i][7]};
        *(float4*)(Crow)     = v0;
        *(float4*)(Crow + 4) = v1;
    }
}

// ---------------------------------------------------------------------------
// RoPE + RMSNorm over a [T, H, 128] tensor in place.
// grid(T, H), block 64: thread i handles the rotation pair (i, i+64)
// ---------------------------------------------------------------------------
__global__ __launch_bounds__(64) void rope_rms_kernel(
    float* __restrict__ X, const float* __restrict__ cosp,
    const float* __restrict__ sinp, int H)
{
    int t = blockIdx.x, h = blockIdx.y;
    int i = threadIdx.x;           // 0..63
    float* xp = X + ((size_t)t * H + h) * HD;

    float x1 = xp[i], x2 = xp[i + HD2];
    float c = cosp[t * HD2 + i];
    float s = sinp[t * HD2 + i];
    float y1 = x1 * c + x2 * s;
    float y2 = x2 * c - x1 * s;

    float ss = y1 * y1 + y2 * y2;
#pragma unroll
    for (int off = 16; off; off >>= 1)
        ss += __shfl_xor_sync(0xffffffffu, ss, off);

    __shared__ float s2[2];
    if ((i & 31) == 0) s2[i >> 5] = ss;
    __syncthreads();
    float tot = s2[0] + s2[1];
    float r = rsqrtf(tot * (1.0f / HD) + 1e-6f);

    xp[i]       = y1 * r;
    xp[i + HD2] = y2 * r;
}

// ---------------------------------------------------------------------------
// Flash attention fp32, causal, GQA (4 Q heads per KV head).
// Block = (64 query rows, 1 head), 128 threads (4 warps).
// Within a warp: row = lane>>1 (+warp*16), half = lane&1 picks d-range [0,64)
// or [64,128). q and O accumulator live in registers (64 floats each).
// K/V tiles of 32 keys in smem; per-tile online softmax.
// ---------------------------------------------------------------------------
#define FA_BQ 64
#define FA_BK 32

__global__ __launch_bounds__(128) void flash_kernel(
    const float* __restrict__ Q, const float* __restrict__ K,
    const float* __restrict__ V, float* __restrict__ O)
{
    __shared__ float Ks[FA_BK][HD];
    __shared__ float Vs[FA_BK][HD];

    int h  = blockIdx.y;
    int hk = h >> 2;               // 16 Q heads -> 4 KV heads
    int qb = blockIdx.x * FA_BQ;
    int tid = threadIdx.x;
    int lane = tid & 31, warp = tid >> 5;
    int row  = warp * 16 + (lane >> 1);
    int half = lane & 1;
    int t  = qb + row;
    int d0 = half * HD2;

    // q half-row into registers
    float q[HD2];
    const float* qptr = Q + ((size_t)t * HQ + h) * HD + d0;
#pragma unroll
    for (int i = 0; i < 16; i++) {
        float4 v = *(const float4*)(qptr + i * 4);
        q[i*4] = v.x; q[i*4+1] = v.y; q[i*4+2] = v.z; q[i*4+3] = v.w;
    }

    float o[HD2];
#pragma unroll
    for (int i = 0; i < HD2; i++) o[i] = 0.f;
    float m = -CUDART_INF_F, l = 0.f;

    const float scale = 0.08838834764831845f;   // 1/sqrt(128)
    int tmax = qb + FA_BQ - 1;

    for (int kb = 0; kb <= tmax; kb += FA_BK) {
        // cooperative K/V tile load: 32 keys x 128 floats each
#pragma unroll
        for (int i = 0; i < 8; i++) {
            int e  = tid + i * 128;       // 0..1023 float4 slots
            int r  = e >> 5;              // key within tile
            int c4 = e & 31;
            const float* kg = K + ((size_t)(kb + r) * HKV + hk) * HD + c4 * 4;
            const float* vg = V + ((size_t)(kb + r) * HKV + hk) * HD + c4 * 4;
            *(float4*)&Ks[r][c4 * 4] = *(const float4*)kg;
            *(float4*)&Vs[r][c4 * 4] = *(const float4*)vg;
        }
        __syncthreads();

        float sv[FA_BK];
#pragma unroll
        for (int j = 0; j < FA_BK; j++) {
            const float* kr = &Ks[j][d0];
            float p = 0.f;
#pragma unroll
            for (int i = 0; i < HD2; i++) p += q[i] * kr[i];
            p += __shfl_xor_sync(0xffffffffu, p, 1);  // combine the two halves
            int sidx = kb + j;
            sv[j] = (sidx <= t) ? p * scale : -CUDART_INF_F;
        }

        float mt = m;
#pragma unroll
        for (int j = 0; j < FA_BK; j++) mt = fmaxf(mt, sv[j]);

        float corr = __expf(m - mt);   // m=-inf on tile 0 -> corr=0, o already 0
        l *= corr;
#pragma unroll
        for (int i = 0; i < HD2; i++) o[i] *= corr;

#pragma unroll
        for (int j = 0; j < FA_BK; j++) {
            float p = __expf(sv[j] - mt);
            l += p;
            const float* vr = &Vs[j][d0];
#pragma unroll
            for (int i = 0; i < HD2; i++) o[i] += p * vr[i];
        }
        m = mt;
        __syncthreads();
    }

    float inv = 1.0f / l;
    float* optr = O + ((size_t)t * HQ + h) * HD + d0;
#pragma unroll
    for (int i = 0; i < 16; i++) {
        float4 v = {o[i*4] * inv, o[i*4+1] * inv, o[i*4+2] * inv, o[i*4+3] * inv};
        *(float4*)(optr + i * 4) = v;
    }
}

// ---------------------------------------------------------------------------
// Launch
// Inputs (metadata order): x, cos, sin, wq, wk, wv, wo ; output f32 [1,T,C]
// ---------------------------------------------------------------------------
extern "C" void kernel_launch(void* const* d_in, const int* in_sizes, int n_in,
                              void* d_out, int out_size)
{
    const float* x   = (const float*)d_in[0];
    const float* cs  = (const float*)d_in[1];
    const float* sn  = (const float*)d_in[2];
    const float* wq  = (const float*)d_in[3];
    const float* wk  = (const float*)d_in[4];
    const float* wv  = (const float*)d_in[5];
    const float* wo  = (const float*)d_in[6];
    float* out = (float*)d_out;

    float *pq, *pk, *pv, *patt;
    cudaGetSymbolAddress((void**)&pq,   g_q);
    cudaGetSymbolAddress((void**)&pk,   g_k);
    cudaGetSymbolAddress((void**)&pv,   g_v);
    cudaGetSymbolAddress((void**)&patt, g_att);

    // QKV projections
    {
        dim3 gq(C_EMB / BN, T_SEQ / BM);
        sgemm_kernel<<<gq, 256>>>(x, wq, pq, T_SEQ, C_EMB, C_EMB);
        dim3 gk((HKV * HD) / BN, T_SEQ / BM);
        sgemm_kernel<<<gk, 256>>>(x, wk, pk, T_SEQ, HKV * HD, C_EMB);
        sgemm_kernel<<<gk, 256>>>(x, wv, pv, T_SEQ, HKV * HD, C_EMB);
    }

    // RoPE + RMSNorm on q and k
    rope_rms_kernel<<<dim3(T_SEQ, HQ),  64>>>(pq, cs, sn, HQ);
    rope_rms_kernel<<<dim3(T_SEQ, HKV), 64>>>(pk, cs, sn, HKV);

    // Flash attention
    flash_kernel<<<dim3(T_SEQ / FA_BQ, HQ), 128>>>(pq, pk, pv, patt);

    // Output projection -> d_out
    {
        dim3 go(C_EMB / BN, T_SEQ / BM);
        sgemm_kernel<<<go, 256>>>(patt, wo, out, T_SEQ, C_EMB, C_EMB);
    }
}

// round 2
// speedup vs baseline: 1.1983x; 1.1983x over previous
#include <cuda_runtime.h>
#include <cuda_bf16.h>
#include <math_constants.h>
#include <cstdint>

// Problem constants
#define T_SEQ 4096
#define C_EMB 2048
#define HQ 16
#define HKV 4
#define HD 128
#define HD2 64

// Scratch (device globals; allocation in kernel_launch is forbidden)
__device__ float g_q[T_SEQ * HQ * HD];     // 32 MB
__device__ float g_k[T_SEQ * HKV * HD];    // 8 MB
__device__ float g_v[T_SEQ * HKV * HD];    // 8 MB
__device__ float g_att[T_SEQ * HQ * HD];   // 32 MB

// ---------------------------------------------------------------------------
// TF32 tensor-core GEMM: C[M,N] = A[M,K] @ B[K,N], row-major.
// Block tile 128x128x32, 256 threads (8 warps), warp tile 32x64.
// mma.sync.aligned.m16n8k8.row.col.f32.tf32.tf32.f32
// Smem row stride 136 floats -> fragment loads hit banks (8r+g)%32: conflict-free.
// ---------------------------------------------------------------------------
#define TM 128
#define TN 128
#define TKK 32
#define SROW 136   // 128 + 8 pad

__device__ __forceinline__ uint32_t f2tf32(float f) {
    uint32_t r;
    asm("cvt.rna.tf32.f32 %0, %1;" : "=r"(r) : "f"(f));
    return r;
}

__device__ __forceinline__ void mma_tf32(float c[4], const uint32_t a[4],
                                         uint32_t b0, uint32_t b1) {
    asm("mma.sync.aligned.m16n8k8.row.col.f32.tf32.tf32.f32 "
        "{%0,%1,%2,%3}, {%4,%5,%6,%7}, {%8,%9}, {%0,%1,%2,%3};"
        : "+f"(c[0]), "+f"(c[1]), "+f"(c[2]), "+f"(c[3])
        : "r"(a[0]), "r"(a[1]), "r"(a[2]), "r"(a[3]), "r"(b0), "r"(b1));
}

__global__ __launch_bounds__(256) void gemm_tf32_kernel(
    const float* __restrict__ A, const float* __restrict__ B,
    float* __restrict__ C, int M, int N, int K)
{
    __shared__ uint32_t As[TKK][SROW];   // [k][m], tf32 bits
    __shared__ uint32_t Bs[TKK][SROW];   // [k][n], tf32 bits

    int tid = threadIdx.x;
    int bx = blockIdx.x, by = blockIdx.y;
    int lane = tid & 31, warp = tid >> 5;
    int wm = (warp >> 1) * 32, wn = (warp & 1) * 64;
    int gr = lane >> 2, tg = lane & 3;

    const float* Ablk = A + (size_t)by * TM * K;
    const float* Bblk = B + (size_t)bx * TN;

    float acc[2][8][4];
#pragma unroll
    for (int i = 0; i < 2; i++)
#pragma unroll
        for (int j = 0; j < 8; j++)
#pragma unroll
            for (int q = 0; q < 4; q++) acc[i][j][q] = 0.f;

    float4 ra[4], rb[4];

    // prologue: load first tile
#pragma unroll
    for (int i = 0; i < 4; i++) {
        int e = tid + i * 256;
        { int r = e >> 3, c4 = e & 7;
          ra[i] = *(const float4*)(Ablk + (size_t)r * K + c4 * 4); }
        { int r = e >> 5, c4 = e & 31;
          rb[i] = *(const float4*)(Bblk + (size_t)r * N + c4 * 4); }
    }
    // store tile 0
#pragma unroll
    for (int i = 0; i < 4; i++) {
        int e = tid + i * 256;
        { int r = e >> 3, c4 = e & 7;
          As[c4*4+0][r] = f2tf32(ra[i].x);
          As[c4*4+1][r] = f2tf32(ra[i].y);
          As[c4*4+2][r] = f2tf32(ra[i].z);
          As[c4*4+3][r] = f2tf32(ra[i].w); }
        { int r = e >> 5, c4 = e & 31;
          uint4 u = { f2tf32(rb[i].x), f2tf32(rb[i].y),
                      f2tf32(rb[i].z), f2tf32(rb[i].w) };
          *(uint4*)&Bs[r][c4 * 4] = u; }
    }
    __syncthreads();

    int nk = K / TKK;
    for (int kt = 0; kt < nk; kt++) {
        // prefetch next tile into registers
        if (kt + 1 < nk) {
            int k0 = (kt + 1) * TKK;
#pragma unroll
            for (int i = 0; i < 4; i++) {
                int e = tid + i * 256;
                { int r = e >> 3, c4 = e & 7;
                  ra[i] = *(const float4*)(Ablk + (size_t)r * K + k0 + c4 * 4); }
                { int r = e >> 5, c4 = e & 31;
                  rb[i] = *(const float4*)(Bblk + (size_t)(k0 + r) * N + c4 * 4); }
            }
        }

        // compute on current smem tile: 4 k-chunks of 8
#pragma unroll
        for (int kk = 0; kk < 4; kk++) {
            int k0 = kk * 8;
            uint32_t a[2][4];
#pragma unroll
            for (int i = 0; i < 2; i++) {
                int m0 = wm + i * 16;
                a[i][0] = As[k0 + tg][m0 + gr];
                a[i][1] = As[k0 + tg][m0 + gr + 8];
                a[i][2] = As[k0 + tg + 4][m0 + gr];
                a[i][3] = As[k0 + tg + 4][m0 + gr + 8];
            }
#pragma unroll
            for (int j = 0; j < 8; j++) {
                uint32_t b0 = Bs[k0 + tg][wn + j * 8 + gr];
                uint32_t b1 = Bs[k0 + tg + 4][wn + j * 8 + gr];
                mma_tf32(acc[0][j], a[0], b0, b1);
                mma_tf32(acc[1][j], a[1], b0, b1);
            }
        }

        if (kt + 1 < nk) {
            __syncthreads();
#pragma unroll
            for (int i = 0; i < 4; i++) {
                int e = tid + i * 256;
                { int r = e >> 3, c4 = e & 7;
                  As[c4*4+0][r] = f2tf32(ra[i].x);
                  As[c4*4+1][r] = f2tf32(ra[i].y);
                  As[c4*4+2][r] = f2tf32(ra[i].z);
                  As[c4*4+3][r] = f2tf32(ra[i].w); }
                { int r = e >> 5, c4 = e & 31;
                  uint4 u = { f2tf32(rb[i].x), f2tf32(rb[i].y),
                              f2tf32(rb[i].z), f2tf32(rb[i].w) };
                  *(uint4*)&Bs[r][c4 * 4] = u; }
            }
            __syncthreads();
        }
    }

    // epilogue: c0,c1 at (row=gr, col=2tg,2tg+1), c2,c3 at row gr+8
#pragma unroll
    for (int i = 0; i < 2; i++) {
#pragma unroll
        for (int j = 0; j < 8; j++) {
            int r0 = by * TM + wm + i * 16 + gr;
            int cc = bx * TN + wn + j * 8 + 2 * tg;
            float2 v0 = { acc[i][j][0], acc[i][j][1] };
            float2 v1 = { acc[i][j][2], acc[i][j][3] };
            *(float2*)(C + (size_t)r0 * N + cc) = v0;
            *(float2*)(C + (size_t)(r0 + 8) * N + cc) = v1;
        }
    }
}

// ---------------------------------------------------------------------------
// RoPE + RMSNorm over a [T, H, 128] tensor in place.
// grid(T, H), block 64: thread i handles the rotation pair (i, i+64)
// ---------------------------------------------------------------------------
__global__ __launch_bounds__(64) void rope_rms_kernel(
    float* __restrict__ X, const float* __restrict__ cosp,
    const float* __restrict__ sinp, int H)
{
    int t = blockIdx.x, h = blockIdx.y;
    int i = threadIdx.x;           // 0..63
    float* xp = X + ((size_t)t * H + h) * HD;

    float x1 = xp[i], x2 = xp[i + HD2];
    float c = cosp[t * HD2 + i];
    float s = sinp[t * HD2 + i];
    float y1 = x1 * c + x2 * s;
    float y2 = x2 * c - x1 * s;

    float ss = y1 * y1 + y2 * y2;
#pragma unroll
    for (int off = 16; off; off >>= 1)
        ss += __shfl_xor_sync(0xffffffffu, ss, off);

    __shared__ float s2[2];
    if ((i & 31) == 0) s2[i >> 5] = ss;
    __syncthreads();
    float tot = s2[0] + s2[1];
    float r = rsqrtf(tot * (1.0f / HD) + 1e-6f);

    xp[i]       = y1 * r;
    xp[i + HD2] = y2 * r;
}

// ---------------------------------------------------------------------------
// Flash attention fp32, causal, GQA (4 Q heads per KV head).
// Block = (64 query rows, 1 head), 128 threads (4 warps).
// ---------------------------------------------------------------------------
#define FA_BQ 64
#define FA_BK 32

__global__ __launch_bounds__(128) void flash_kernel(
    const float* __restrict__ Q, const float* __restrict__ K,
    const float* __restrict__ V, float* __restrict__ O)
{
    __shared__ float Ks[FA_BK][HD];
    __shared__ float Vs[FA_BK][HD];

    int h  = blockIdx.y;
    int hk = h >> 2;               // 16 Q heads -> 4 KV heads
    int qb = blockIdx.x * FA_BQ;
    int tid = threadIdx.x;
    int lane = tid & 31, warp = tid >> 5;
    int row  = warp * 16 + (lane >> 1);
    int half = lane & 1;
    int t  = qb + row;
    int d0 = half * HD2;

    float q[HD2];
    const float* qptr = Q + ((size_t)t * HQ + h) * HD + d0;
#pragma unroll
    for (int i = 0; i < 16; i++) {
        float4 v = *(const float4*)(qptr + i * 4);
        q[i*4] = v.x; q[i*4+1] = v.y; q[i*4+2] = v.z; q[i*4+3] = v.w;
    }

    float o[HD2];
#pragma unroll
    for (int i = 0; i < HD2; i++) o[i] = 0.f;
    float m = -CUDART_INF_F, l = 0.f;

    const float scale = 0.08838834764831845f;   // 1/sqrt(128)
    int tmax = qb + FA_BQ - 1;

    for (int kb = 0; kb <= tmax; kb += FA_BK) {
#pragma unroll
        for (int i = 0; i < 8; i++) {
            int e  = tid + i * 128;
            int r  = e >> 5;
            int c4 = e & 31;
            const float* kg = K + ((size_t)(kb + r) * HKV + hk) * HD + c4 * 4;
            const float* vg = V + ((size_t)(kb + r) * HKV + hk) * HD + c4 * 4;
            *(float4*)&Ks[r][c4 * 4] = *(const float4*)kg;
            *(float4*)&Vs[r][c4 * 4] = *(const float4*)vg;
        }
        __syncthreads();

        float sv[FA_BK];
#pragma unroll
        for (int j = 0; j < FA_BK; j++) {
            const float* kr = &Ks[j][d0];
            float p = 0.f;
#pragma unroll
            for (int i = 0; i < HD2; i++) p += q[i] * kr[i];
            p += __shfl_xor_sync(0xffffffffu, p, 1);
            int sidx = kb + j;
            sv[j] = (sidx <= t) ? p * scale : -CUDART_INF_F;
        }

        float mt = m;
#pragma unroll
        for (int j = 0; j < FA_BK; j++) mt = fmaxf(mt, sv[j]);

        float corr = __expf(m - mt);
        l *= corr;
#pragma unroll
        for (int i = 0; i < HD2; i++) o[i] *= corr;

#pragma unroll
        for (int j = 0; j < FA_BK; j++) {
            float p = __expf(sv[j] - mt);
            l += p;
            const float* vr = &Vs[j][d0];
#pragma unroll
            for (int i = 0; i < HD2; i++) o[i] += p * vr[i];
        }
        m = mt;
        __syncthreads();
    }

    float inv = 1.0f / l;
    float* optr = O + ((size_t)t * HQ + h) * HD + d0;
#pragma unroll
    for (int i = 0; i < 16; i++) {
        float4 v = {o[i*4] * inv, o[i*4+1] * inv, o[i*4+2] * inv, o[i*4+3] * inv};
        *(float4*)(optr + i * 4) = v;
    }
}

// ---------------------------------------------------------------------------
// Launch
// Inputs (metadata order): x, cos, sin, wq, wk, wv, wo ; output f32 [1,T,C]
// ---------------------------------------------------------------------------
extern "C" void kernel_launch(void* const* d_in, const int* in_sizes, int n_in,
                              void* d_out, int out_size)
{
    const float* x   = (const float*)d_in[0];
    const float* cs  = (const float*)d_in[1];
    const float* sn  = (const float*)d_in[2];
    const float* wq  = (const float*)d_in[3];
    const float* wk  = (const float*)d_in[4];
    const float* wv  = (const float*)d_in[5];
    const float* wo  = (const float*)d_in[6];
    float* out = (float*)d_out;

    float *pq, *pk, *pv, *patt;
    cudaGetSymbolAddress((void**)&pq,   g_q);
    cudaGetSymbolAddress((void**)&pk,   g_k);
    cudaGetSymbolAddress((void**)&pv,   g_v);
    cudaGetSymbolAddress((void**)&patt, g_att);

    // QKV projections (TF32 tensor cores)
    {
        dim3 gq(C_EMB / TN, T_SEQ / TM);
        gemm_tf32_kernel<<<gq, 256>>>(x, wq, pq, T_SEQ, C_EMB, C_EMB);
        dim3 gk((HKV * HD) / TN, T_SEQ / TM);
        gemm_tf32_kernel<<<gk, 256>>>(x, wk, pk, T_SEQ, HKV * HD, C_EMB);
        gemm_tf32_kernel<<<gk, 256>>>(x, wv, pv, T_SEQ, HKV * HD, C_EMB);
    }

    // RoPE + RMSNorm on q and k
    rope_rms_kernel<<<dim3(T_SEQ, HQ),  64>>>(pq, cs, sn, HQ);
    rope_rms_kernel<<<dim3(T_SEQ, HKV), 64>>>(pk, cs, sn, HKV);

    // Flash attention
    flash_kernel<<<dim3(T_SEQ / FA_BQ, HQ), 128>>>(pq, pk, pv, patt);

    // Output projection -> d_out
    {
        dim3 go(C_EMB / TN, T_SEQ / TM);
        gemm_tf32_kernel<<<go, 256>>>(patt, wo, out, T_SEQ, C_EMB, C_EMB);
    }
}

// round 4
// speedup vs baseline: 3.7733x; 3.1488x over previous
#include <cuda_runtime.h>
#include <cuda_bf16.h>
#include <math_constants.h>
#include <cstdint>

// Problem constants
#define T_SEQ 4096
#define C_EMB 2048
#define HQ 16
#define HKV 4
#define HD 128
#define HD2 64

// Scratch (device globals; allocation in kernel_launch is forbidden)
__device__ float g_q[T_SEQ * HQ * HD];     // 32 MB
__device__ float g_k[T_SEQ * HKV * HD];    // 8 MB
__device__ float g_v[T_SEQ * HKV * HD];    // 8 MB
__device__ float g_att[T_SEQ * HQ * HD];   // 32 MB

__device__ __forceinline__ uint32_t f2tf32(float f) {
    uint32_t r;
    asm("cvt.rna.tf32.f32 %0, %1;" : "=r"(r) : "f"(f));
    return r;
}

__device__ __forceinline__ void mma_tf32(float c[4], const uint32_t a[4],
                                         uint32_t b0, uint32_t b1) {
    asm("mma.sync.aligned.m16n8k8.row.col.f32.tf32.tf32.f32 "
        "{%0,%1,%2,%3}, {%4,%5,%6,%7}, {%8,%9}, {%0,%1,%2,%3};"
        : "+f"(c[0]), "+f"(c[1]), "+f"(c[2]), "+f"(c[3])
        : "r"(a[0]), "r"(a[1]), "r"(a[2]), "r"(a[3]), "r"(b0), "r"(b1));
}

// ---------------------------------------------------------------------------
// TF32 tensor-core GEMM: C[M,N] = A[M,K] @ B[K,N], row-major.
// Block tile 128x128x32, 256 threads (8 warps), warp tile 32x64.
// ---------------------------------------------------------------------------
#define TM 128
#define TN 128
#define TKK 32
#define SROW 136   // 128 + 8 pad

__global__ __launch_bounds__(256) void gemm_tf32_kernel(
    const float* __restrict__ A, const float* __restrict__ B,
    float* __restrict__ C, int M, int N, int K)
{
    __shared__ uint32_t As[TKK][SROW];   // [k][m], tf32 bits
    __shared__ uint32_t Bs[TKK][SROW];   // [k][n], tf32 bits

    int tid = threadIdx.x;
    int bx = blockIdx.x, by = blockIdx.y;
    int lane = tid & 31, warp = tid >> 5;
    int wm = (warp >> 1) * 32, wn = (warp & 1) * 64;
    int gr = lane >> 2, tg = lane & 3;

    const float* Ablk = A + (size_t)by * TM * K;
    const float* Bblk = B + (size_t)bx * TN;

    float acc[2][8][4];
#pragma unroll
    for (int i = 0; i < 2; i++)
#pragma unroll
        for (int j = 0; j < 8; j++)
#pragma unroll
            for (int q = 0; q < 4; q++) acc[i][j][q] = 0.f;

    float4 ra[4], rb[4];

#pragma unroll
    for (int i = 0; i < 4; i++) {
        int e = tid + i * 256;
        { int r = e >> 3, c4 = e & 7;
          ra[i] = *(const float4*)(Ablk + (size_t)r * K + c4 * 4); }
        { int r = e >> 5, c4 = e & 31;
          rb[i] = *(const float4*)(Bblk + (size_t)r * N + c4 * 4); }
    }
#pragma unroll
    for (int i = 0; i < 4; i++) {
        int e = tid + i * 256;
        { int r = e >> 3, c4 = e & 7;
          As[c4*4+0][r] = f2tf32(ra[i].x);
          As[c4*4+1][r] = f2tf32(ra[i].y);
          As[c4*4+2][r] = f2tf32(ra[i].z);
          As[c4*4+3][r] = f2tf32(ra[i].w); }
        { int r = e >> 5, c4 = e & 31;
          uint4 u = { f2tf32(rb[i].x), f2tf32(rb[i].y),
                      f2tf32(rb[i].z), f2tf32(rb[i].w) };
          *(uint4*)&Bs[r][c4 * 4] = u; }
    }
    __syncthreads();

    int nk = K / TKK;
    for (int kt = 0; kt < nk; kt++) {
        if (kt + 1 < nk) {
            int k0 = (kt + 1) * TKK;
#pragma unroll
            for (int i = 0; i < 4; i++) {
                int e = tid + i * 256;
                { int r = e >> 3, c4 = e & 7;
                  ra[i] = *(const float4*)(Ablk + (size_t)r * K + k0 + c4 * 4); }
                { int r = e >> 5, c4 = e & 31;
                  rb[i] = *(const float4*)(Bblk + (size_t)(k0 + r) * N + c4 * 4); }
            }
        }

#pragma unroll
        for (int kk = 0; kk < 4; kk++) {
            int k0 = kk * 8;
            uint32_t a[2][4];
#pragma unroll
            for (int i = 0; i < 2; i++) {
                int m0 = wm + i * 16;
                a[i][0] = As[k0 + tg][m0 + gr];
                a[i][1] = As[k0 + tg][m0 + gr + 8];
                a[i][2] = As[k0 + tg + 4][m0 + gr];
                a[i][3] = As[k0 + tg + 4][m0 + gr + 8];
            }
#pragma unroll
            for (int j = 0; j < 8; j++) {
                uint32_t b0 = Bs[k0 + tg][wn + j * 8 + gr];
                uint32_t b1 = Bs[k0 + tg + 4][wn + j * 8 + gr];
                mma_tf32(acc[0][j], a[0], b0, b1);
                mma_tf32(acc[1][j], a[1], b0, b1);
            }
        }

        if (kt + 1 < nk) {
            __syncthreads();
#pragma unroll
            for (int i = 0; i < 4; i++) {
                int e = tid + i * 256;
                { int r = e >> 3, c4 = e & 7;
                  As[c4*4+0][r] = f2tf32(ra[i].x);
                  As[c4*4+1][r] = f2tf32(ra[i].y);
                  As[c4*4+2][r] = f2tf32(ra[i].z);
                  As[c4*4+3][r] = f2tf32(ra[i].w); }
                { int r = e >> 5, c4 = e & 31;
                  uint4 u = { f2tf32(rb[i].x), f2tf32(rb[i].y),
                              f2tf32(rb[i].z), f2tf32(rb[i].w) };
                  *(uint4*)&Bs[r][c4 * 4] = u; }
            }
            __syncthreads();
        }
    }

#pragma unroll
    for (int i = 0; i < 2; i++) {
#pragma unroll
        for (int j = 0; j < 8; j++) {
            int r0 = by * TM + wm + i * 16 + gr;
            int cc = bx * TN + wn + j * 8 + 2 * tg;
            float2 v0 = { acc[i][j][0], acc[i][j][1] };
            float2 v1 = { acc[i][j][2], acc[i][j][3] };
            *(float2*)(C + (size_t)r0 * N + cc) = v0;
            *(float2*)(C + (size_t)(r0 + 8) * N + cc) = v1;
        }
    }
}

// ---------------------------------------------------------------------------
// RoPE + RMSNorm over a [T, H, 128] tensor in place.
// ---------------------------------------------------------------------------
__global__ __launch_bounds__(64) void rope_rms_kernel(
    float* __restrict__ X, const float* __restrict__ cosp,
    const float* __restrict__ sinp, int H)
{
    int t = blockIdx.x, h = blockIdx.y;
    int i = threadIdx.x;           // 0..63
    float* xp = X + ((size_t)t * H + h) * HD;

    float x1 = xp[i], x2 = xp[i + HD2];
    float c = cosp[t * HD2 + i];
    float s = sinp[t * HD2 + i];
    float y1 = x1 * c + x2 * s;
    float y2 = x2 * c - x1 * s;

    float ss = y1 * y1 + y2 * y2;
#pragma unroll
    for (int off = 16; off; off >>= 1)
        ss += __shfl_xor_sync(0xffffffffu, ss, off);

    __shared__ float s2[2];
    if ((i & 31) == 0) s2[i >> 5] = ss;
    __syncthreads();
    float tot = s2[0] + s2[1];
    float r = rsqrtf(tot * (1.0f / HD) + 1e-6f);

    xp[i]       = y1 * r;
    xp[i + HD2] = y2 * r;
}

// ---------------------------------------------------------------------------
// TF32 tensor-core flash attention, causal, GQA.
// Block = (64 q-rows, 1 head), 4 warps; warp owns 16 rows.
// Q frags in regs (scale folded), K/V tiles (32 keys) in smem tf32,
// P staged through smem tf32 for the PV mma. Softmax fp32.
// ---------------------------------------------------------------------------
#define FBQ 64
#define FBK 32
#define KST 132
#define VST 136
#define PST 36

__global__ __launch_bounds__(128) void flash_tf32_kernel(
    const float* __restrict__ Q, const float* __restrict__ K,
    const float* __restrict__ V, float* __restrict__ O)
{
    __shared__ uint32_t Ks[FBK][KST];   // [key][dim]
    __shared__ uint32_t Vs[FBK][VST];   // [key][dim]
    __shared__ uint32_t Ps[FBQ][PST];   // [row][key]

    int h  = blockIdx.y;
    int hk = h >> 2;
    int qb = blockIdx.x * FBQ;
    int tid = threadIdx.x;
    int lane = tid & 31, warp = tid >> 5;
    int wm = warp * 16;
    int gr = lane >> 2, tg = lane & 3;

    const float scale = 0.08838834764831845f;   // 1/sqrt(128)

    // Q fragments (scale folded in before tf32 rounding)
    uint32_t qf[16][4];
    int t0 = qb + wm + gr;
    int t1 = t0 + 8;
    const float* q0 = Q + ((size_t)t0 * HQ + h) * HD;
    const float* q1 = Q + ((size_t)t1 * HQ + h) * HD;
#pragma unroll
    for (int ks = 0; ks < 16; ks++) {
        int c = ks * 8 + tg;
        qf[ks][0] = f2tf32(q0[c] * scale);
        qf[ks][1] = f2tf32(q1[c] * scale);
        qf[ks][2] = f2tf32(q0[c + 4] * scale);
        qf[ks][3] = f2tf32(q1[c + 4] * scale);
    }

    float oacc[16][4];
#pragma unroll
    for (int f = 0; f < 16; f++)
#pragma unroll
        for (int q = 0; q < 4; q++) oacc[f][q] = 0.f;
    float m0 = -CUDART_INF_F, m1 = -CUDART_INF_F;
    float l0 = 0.f, l1 = 0.f;

    int tmax = qb + FBQ - 1;

    for (int kb = 0; kb <= tmax; kb += FBK) {
        // load K/V tile (32 keys x 128 dims), tf32-convert
#pragma unroll
        for (int i = 0; i < 8; i++) {
            int e  = tid + i * 128;
            int r  = e >> 5;
            int c4 = e & 31;
            const float* kg = K + ((size_t)(kb + r) * HKV + hk) * HD + c4 * 4;
            const float* vg = V + ((size_t)(kb + r) * HKV + hk) * HD + c4 * 4;
            float4 kv = *(const float4*)kg;
            float4 vv = *(const float4*)vg;
            uint4 ku = { f2tf32(kv.x), f2tf32(kv.y), f2tf32(kv.z), f2tf32(kv.w) };
            uint4 vu = { f2tf32(vv.x), f2tf32(vv.y), f2tf32(vv.z), f2tf32(vv.w) };
            *(uint4*)&Ks[r][c4 * 4] = ku;
            *(uint4*)&Vs[r][c4 * 4] = vu;
        }
        __syncthreads();

        // S = (Q*scale) @ K^T
        float sacc[4][4];
#pragma unroll
        for (int j = 0; j < 4; j++)
#pragma unroll
            for (int q = 0; q < 4; q++) sacc[j][q] = 0.f;

#pragma unroll
        for (int ks = 0; ks < 16; ks++) {
            int k0 = ks * 8;
#pragma unroll
            for (int j = 0; j < 4; j++) {
                uint32_t b0 = Ks[j * 8 + gr][k0 + tg];
                uint32_t b1 = Ks[j * 8 + gr][k0 + 4 + tg];
                mma_tf32(sacc[j], qf[ks], b0, b1);
            }
        }

        // causal mask + row max (per-thread rows t0, t1)
        float tm0 = -CUDART_INF_F, tm1 = -CUDART_INF_F;
#pragma unroll
        for (int j = 0; j < 4; j++) {
            int kcol = kb + j * 8 + 2 * tg;
            if (kcol     > t0) sacc[j][0] = -CUDART_INF_F;
            if (kcol + 1 > t0) sacc[j][1] = -CUDART_INF_F;
            if (kcol     > t1) sacc[j][2] = -CUDART_INF_F;
            if (kcol + 1 > t1) sacc[j][3] = -CUDART_INF_F;
            tm0 = fmaxf(tm0, fmaxf(sacc[j][0], sacc[j][1]));
            tm1 = fmaxf(tm1, fmaxf(sacc[j][2], sacc[j][3]));
        }
        tm0 = fmaxf(tm0, __shfl_xor_sync(0xffffffffu, tm0, 1));
        tm0 = fmaxf(tm0, __shfl_xor_sync(0xffffffffu, tm0, 2));
        tm1 = fmaxf(tm1, __shfl_xor_sync(0xffffffffu, tm1, 1));
        tm1 = fmaxf(tm1, __shfl_xor_sync(0xffffffffu, tm1, 2));

        float mn0 = fmaxf(m0, tm0);
        float mn1 = fmaxf(m1, tm1);
        float c0 = __expf(m0 - mn0);    // first tile: exp(-inf)=0, oacc already 0
        float c1 = __expf(m1 - mn1);

        float ps0 = 0.f, ps1 = 0.f;
#pragma unroll
        for (int j = 0; j < 4; j++) {
            uint32_t p0 = f2tf32(__expf(sacc[j][0] - mn0));
            uint32_t p1 = f2tf32(__expf(sacc[j][1] - mn0));
            uint32_t p2 = f2tf32(__expf(sacc[j][2] - mn1));
            uint32_t p3 = f2tf32(__expf(sacc[j][3] - mn1));
            ps0 += __uint_as_float(p0) + __uint_as_float(p1);
            ps1 += __uint_as_float(p2) + __uint_as_float(p3);
            uint2 w0 = { p0, p1 };
            uint2 w1 = { p2, p3 };
            *(uint2*)&Ps[wm + gr][j * 8 + 2 * tg]     = w0;
            *(uint2*)&Ps[wm + 8 + gr][j * 8 + 2 * tg] = w1;
        }
        ps0 += __shfl_xor_sync(0xffffffffu, ps0, 1);
        ps0 += __shfl_xor_sync(0xffffffffu, ps0, 2);
        ps1 += __shfl_xor_sync(0xffffffffu, ps1, 1);
        ps1 += __shfl_xor_sync(0xffffffffu, ps1, 2);

        l0 = l0 * c0 + ps0;
        l1 = l1 * c1 + ps1;
        m0 = mn0; m1 = mn1;

#pragma unroll
        for (int f = 0; f < 16; f++) {
            oacc[f][0] *= c0; oacc[f][1] *= c0;
            oacc[f][2] *= c1; oacc[f][3] *= c1;
        }
        __syncwarp();   // P writes visible within warp

        // O += P @ V
#pragma unroll
        for (int ks2 = 0; ks2 < 4; ks2++) {
            int k0 = ks2 * 8;
            uint32_t a[4];
            a[0] = Ps[wm + gr][k0 + tg];
            a[1] = Ps[wm + 8 + gr][k0 + tg];
            a[2] = Ps[wm + gr][k0 + 4 + tg];
            a[3] = Ps[wm + 8 + gr][k0 + 4 + tg];
#pragma unroll
            for (int f = 0; f < 16; f++) {
                uint32_t b0 = Vs[k0 + tg][f * 8 + gr];
                uint32_t b1 = Vs[k0 + 4 + tg][f * 8 + gr];
                mma_tf32(oacc[f], a, b0, b1);
            }
        }
        __syncthreads();   // protect Ks/Vs before next tile load
    }

    float inv0 = 1.0f / l0;
    float inv1 = 1.0f / l1;
    float* o0 = O + ((size_t)t0 * HQ + h) * HD;
    float* o1 = O + ((size_t)t1 * HQ + h) * HD;
#pragma unroll
    for (int f = 0; f < 16; f++) {
        int cc = f * 8 + 2 * tg;
        float2 v0 = { oacc[f][0] * inv0, oacc[f][1] * inv0 };
        float2 v1 = { oacc[f][2] * inv1, oacc[f][3] * inv1 };
        *(float2*)(o0 + cc) = v0;
        *(float2*)(o1 + cc) = v1;
    }
}

// ---------------------------------------------------------------------------
// Launch
// ---------------------------------------------------------------------------
extern "C" void kernel_launch(void* const* d_in, const int* in_sizes, int n_in,
                              void* d_out, int out_size)
{
    const float* x   = (const float*)d_in[0];
    const float* cs  = (const float*)d_in[1];
    const float* sn  = (const float*)d_in[2];
    const float* wq  = (const float*)d_in[3];
    const float* wk  = (const float*)d_in[4];
    const float* wv  = (const float*)d_in[5];
    const float* wo  = (const float*)d_in[6];
    float* out = (float*)d_out;

    float *pq, *pk, *pv, *patt;
    cudaGetSymbolAddress((void**)&pq,   g_q);
    cudaGetSymbolAddress((void**)&pk,   g_k);
    cudaGetSymbolAddress((void**)&pv,   g_v);
    cudaGetSymbolAddress((void**)&patt, g_att);

    // QKV projections (TF32 tensor cores)
    {
        dim3 gq(C_EMB / TN, T_SEQ / TM);
        gemm_tf32_kernel<<<gq, 256>>>(x, wq, pq, T_SEQ, C_EMB, C_EMB);
        dim3 gk((HKV * HD) / TN, T_SEQ / TM);
        gemm_tf32_kernel<<<gk, 256>>>(x, wk, pk, T_SEQ, HKV * HD, C_EMB);
        gemm_tf32_kernel<<<gk, 256>>>(x, wv, pv, T_SEQ, HKV * HD, C_EMB);
    }

    // RoPE + RMSNorm on q and k
    rope_rms_kernel<<<dim3(T_SEQ, HQ),  64>>>(pq, cs, sn, HQ);
    rope_rms_kernel<<<dim3(T_SEQ, HKV), 64>>>(pk, cs, sn, HKV);

    // Flash attention (TF32 tensor cores)
    flash_tf32_kernel<<<dim3(T_SEQ / FBQ, HQ), 128>>>(pq, pk, pv, patt);

    // Output projection -> d_out
    {
        dim3 go(C_EMB / TN, T_SEQ / TM);
        gemm_tf32_kernel<<<go, 256>>>(patt, wo, out, T_SEQ, C_EMB, C_EMB);
    }
}

// round 5
// speedup vs baseline: 5.4773x; 1.4516x over previous
#include <cuda_runtime.h>
#include <cuda_bf16.h>
#include <math_constants.h>
#include <cstdint>

// Problem constants
#define T_SEQ 4096
#define C_EMB 2048
#define HQ 16
#define HKV 4
#define HD 128
#define HD2 64
#define KVD 512   // HKV*HD

// Scratch (device globals; allocation in kernel_launch is forbidden)
__device__ float g_q[T_SEQ * HQ * HD];
__device__ float g_k[T_SEQ * KVD];
__device__ float g_v[T_SEQ * KVD];
__device__ float g_att[T_SEQ * C_EMB];
__device__ float g_xr[T_SEQ * C_EMB];      // tf32-rounded copies
__device__ float g_wqr[C_EMB * C_EMB];
__device__ float g_wkr[C_EMB * KVD];
__device__ float g_wvr[C_EMB * KVD];
__device__ float g_wor[C_EMB * C_EMB];

__device__ __forceinline__ uint32_t f2tf32(float f) {
    uint32_t r;
    asm("cvt.rna.tf32.f32 %0, %1;" : "=r"(r) : "f"(f));
    return r;
}

__device__ __forceinline__ void mma_tf32(float c[4], const uint32_t a[4],
                                         uint32_t b0, uint32_t b1) {
    asm("mma.sync.aligned.m16n8k8.row.col.f32.tf32.tf32.f32 "
        "{%0,%1,%2,%3}, {%4,%5,%6,%7}, {%8,%9}, {%0,%1,%2,%3};"
        : "+f"(c[0]), "+f"(c[1]), "+f"(c[2]), "+f"(c[3])
        : "r"(a[0]), "r"(a[1]), "r"(a[2]), "r"(a[3]), "r"(b0), "r"(b1));
}

__device__ __forceinline__ void cp_async16(float* smem_dst, const float* gsrc) {
    uint32_t s = (uint32_t)__cvta_generic_to_shared(smem_dst);
    asm volatile("cp.async.cg.shared.global [%0], [%1], 16;\n" :: "r"(s), "l"(gsrc));
}
__device__ __forceinline__ void cp_commit() {
    asm volatile("cp.async.commit_group;\n");
}
__device__ __forceinline__ void cp_wait1() {
    asm volatile("cp.async.wait_group 1;\n");
}
__device__ __forceinline__ void cp_wait2() {
    asm volatile("cp.async.wait_group 2;\n");
}

// ---------------------------------------------------------------------------
// Elementwise tf32 rounding pass (vectorized). n4 = element count / 4.
// ---------------------------------------------------------------------------
__global__ __launch_bounds__(256) void round_kernel(
    const float* __restrict__ in, float* __restrict__ out, int n4)
{
    int i = blockIdx.x * blockDim.x + threadIdx.x;
    if (i < n4) {
        float4 v = ((const float4*)in)[i];
        v.x = __uint_as_float(f2tf32(v.x));
        v.y = __uint_as_float(f2tf32(v.y));
        v.z = __uint_as_float(f2tf32(v.z));
        v.w = __uint_as_float(f2tf32(v.w));
        ((float4*)out)[i] = v;
    }
}

// ---------------------------------------------------------------------------
// TF32 GEMM with cp.async 3-stage pipeline. Inputs pre-rounded to tf32.
// C[M,N] = A[M,K] @ B[K,N]. Block 128x128x32, 256 thr, warp tile 32x64.
// As [m][k] stride 36 (conflict-free: bank=4gr+tg), Bs [k][n] stride 136
// (bank=8tg+gr). Both strides keep 16B row alignment for cp.async.
// ---------------------------------------------------------------------------
#define BM 128
#define BN 128
#define BK 32
#define AST 36
#define BST 136
#define AWORDS (BM * AST)                  // 4608
#define GSTGW (AWORDS + BK * BST)          // 8960 words
#define GEMM_SMEM (GSTGW * 3 * 4)          // 107520 bytes

__global__ __launch_bounds__(256) void gemm_async(
    const float* __restrict__ A, const float* __restrict__ B,
    float* __restrict__ C, int M, int N, int K)
{
    extern __shared__ __align__(16) float sm[];

    int tid = threadIdx.x;
    int bx = blockIdx.x, by = blockIdx.y;
    int lane = tid & 31, warp = tid >> 5;
    int wm = (warp >> 1) * 32, wn = (warp & 1) * 64;
    int gr = lane >> 2, tg = lane & 3;

    const float* Ab = A + (size_t)by * BM * K;
    const float* Bb = B + (size_t)bx * BN;

    auto issue = [&](int kt, int s) {
        float* As = sm + s * GSTGW;
        float* Bs = As + AWORDS;
        int k0 = kt * BK;
#pragma unroll
        for (int i = 0; i < 4; i++) {
            int c = tid + i * 256;
            int r = c >> 3, cc = c & 7;
            cp_async16(As + r * AST + cc * 4, Ab + (size_t)r * K + k0 + cc * 4);
        }
#pragma unroll
        for (int i = 0; i < 4; i++) {
            int c = tid + i * 256;
            int r = c >> 5, cc = c & 31;
            cp_async16(Bs + r * BST + cc * 4, Bb + (size_t)(k0 + r) * N + cc * 4);
        }
        cp_commit();
    };

    float acc[2][8][4];
#pragma unroll
    for (int i = 0; i < 2; i++)
#pragma unroll
        for (int j = 0; j < 8; j++)
#pragma unroll
            for (int q = 0; q < 4; q++) acc[i][j][q] = 0.f;

    int nk = K / BK;
    issue(0, 0);
    issue(1, 1);

    for (int kt = 0; kt < nk; kt++) {
        if (kt + 2 < nk) issue(kt + 2, (kt + 2) % 3);
        else cp_commit();          // keep group count uniform for wait_group 2
        cp_wait2();
        __syncthreads();

        const float* As = sm + (kt % 3) * GSTGW;
        const float* Bs = As + AWORDS;

#pragma unroll
        for (int kk = 0; kk < 4; kk++) {
            int k0 = kk * 8;
            uint32_t a[2][4];
#pragma unroll
            for (int i = 0; i < 2; i++) {
                int m0 = wm + i * 16 + gr;
                a[i][0] = __float_as_uint(As[m0 * AST + k0 + tg]);
                a[i][1] = __float_as_uint(As[(m0 + 8) * AST + k0 + tg]);
                a[i][2] = __float_as_uint(As[m0 * AST + k0 + tg + 4]);
                a[i][3] = __float_as_uint(As[(m0 + 8) * AST + k0 + tg + 4]);
            }
#pragma unroll
            for (int j = 0; j < 8; j++) {
                uint32_t b0 = __float_as_uint(Bs[(k0 + tg) * BST + wn + j * 8 + gr]);
                uint32_t b1 = __float_as_uint(Bs[(k0 + tg + 4) * BST + wn + j * 8 + gr]);
                mma_tf32(acc[0][j], a[0], b0, b1);
                mma_tf32(acc[1][j], a[1], b0, b1);
            }
        }
        __syncthreads();   // all warps done before stage overwrite next iter
    }

#pragma unroll
    for (int i = 0; i < 2; i++) {
#pragma unroll
        for (int j = 0; j < 8; j++) {
            int r0 = by * BM + wm + i * 16 + gr;
            int cc = bx * BN + wn + j * 8 + 2 * tg;
            float2 v0 = { acc[i][j][0], acc[i][j][1] };
            float2 v1 = { acc[i][j][2], acc[i][j][3] };
            *(float2*)(C + (size_t)r0 * N + cc) = v0;
            *(float2*)(C + (size_t)(r0 + 8) * N + cc) = v1;
        }
    }
}

// ---------------------------------------------------------------------------
// RoPE + RMSNorm over a [T, H, 128] tensor in place; optional tf32 rounding
// of the output (used for K so flash can cp.async it raw).
// ---------------------------------------------------------------------------
__global__ __launch_bounds__(64) void rope_rms_kernel(
    float* __restrict__ X, const float* __restrict__ cosp,
    const float* __restrict__ sinp, int H, int do_round)
{
    int t = blockIdx.x, h = blockIdx.y;
    int i = threadIdx.x;           // 0..63
    float* xp = X + ((size_t)t * H + h) * HD;

    float x1 = xp[i], x2 = xp[i + HD2];
    float c = cosp[t * HD2 + i];
    float s = sinp[t * HD2 + i];
    float y1 = x1 * c + x2 * s;
    float y2 = x2 * c - x1 * s;

    float ss = y1 * y1 + y2 * y2;
#pragma unroll
    for (int off = 16; off; off >>= 1)
        ss += __shfl_xor_sync(0xffffffffu, ss, off);

    __shared__ float s2[2];
    if ((i & 31) == 0) s2[i >> 5] = ss;
    __syncthreads();
    float tot = s2[0] + s2[1];
    float r = rsqrtf(tot * (1.0f / HD) + 1e-6f);

    float o1 = y1 * r, o2 = y2 * r;
    if (do_round) {
        o1 = __uint_as_float(f2tf32(o1));
        o2 = __uint_as_float(f2tf32(o2));
    }
    xp[i]       = o1;
    xp[i + HD2] = o2;
}

// ---------------------------------------------------------------------------
// TF32 flash attention with cp.async double-buffered K/V (pre-rounded).
// Block = (64 q-rows, 1 head), 4 warps. Q frags in regs (scale folded),
// P staged through smem tf32. Softmax fp32.
// ---------------------------------------------------------------------------
#define FBQ 64
#define FBK 32
#define KSTW 132
#define VSTW 136
#define FSTGW (FBK * KSTW + FBK * VSTW)     // 8576 words / stage
#define PSOFF (2 * FSTGW)                   // 17152
#define PST 36
#define FLASH_SMEM ((PSOFF + FBQ * PST) * 4)  // 77824 bytes

__global__ __launch_bounds__(128) void flash_async(
    const float* __restrict__ Q, const float* __restrict__ K,
    const float* __restrict__ V, float* __restrict__ O)
{
    extern __shared__ __align__(16) float sm[];

    int h  = blockIdx.y;
    int hk = h >> 2;
    int qb = blockIdx.x * FBQ;
    int tid = threadIdx.x;
    int lane = tid & 31, warp = tid >> 5;
    int wm = warp * 16;
    int gr = lane >> 2, tg = lane & 3;

    auto issue = [&](int it, int s) {
        float* Ks = sm + s * FSTGW;
        float* Vs = Ks + FBK * KSTW;
        int kb = it * FBK;
#pragma unroll
        for (int i = 0; i < 8; i++) {
            int c = tid + i * 128;
            int r = c >> 5, cc = c & 31;
            const float* kg = K + ((size_t)(kb + r) * HKV + hk) * HD + cc * 4;
            const float* vg = V + ((size_t)(kb + r) * HKV + hk) * HD + cc * 4;
            cp_async16(Ks + r * KSTW + cc * 4, kg);
            cp_async16(Vs + r * VSTW + cc * 4, vg);
        }
        cp_commit();
    };

    const float scale = 0.08838834764831845f;   // 1/sqrt(128)

    // Q fragments (scale folded in before tf32 rounding)
    uint32_t qf[16][4];
    int t0 = qb + wm + gr;
    int t1 = t0 + 8;
    const float* q0 = Q + ((size_t)t0 * HQ + h) * HD;
    const float* q1 = Q + ((size_t)t1 * HQ + h) * HD;
#pragma unroll
    for (int ks = 0; ks < 16; ks++) {
        int c = ks * 8 + tg;
        qf[ks][0] = f2tf32(q0[c] * scale);
        qf[ks][1] = f2tf32(q1[c] * scale);
        qf[ks][2] = f2tf32(q0[c + 4] * scale);
        qf[ks][3] = f2tf32(q1[c + 4] * scale);
    }

    float oacc[16][4];
#pragma unroll
    for (int f = 0; f < 16; f++)
#pragma unroll
        for (int q = 0; q < 4; q++) oacc[f][q] = 0.f;
    float m0 = -CUDART_INF_F, m1 = -CUDART_INF_F;
    float l0 = 0.f, l1 = 0.f;

    int nt = (qb + FBQ) / FBK;   // tiles 0..nt-1
    issue(0, 0);

    for (int it = 0; it < nt; it++) {
        if (it + 1 < nt) issue(it + 1, (it + 1) & 1);
        else cp_commit();
        cp_wait1();
        __syncthreads();

        const float* Ks = sm + (it & 1) * FSTGW;
        const float* Vs = Ks + FBK * KSTW;
        float* Ps = sm + PSOFF;
        int kb = it * FBK;

        // S = (Q*scale) @ K^T
        float sacc[4][4];
#pragma unroll
        for (int j = 0; j < 4; j++)
#pragma unroll
            for (int q = 0; q < 4; q++) sacc[j][q] = 0.f;

#pragma unroll
        for (int ks = 0; ks < 16; ks++) {
            int k0 = ks * 8;
#pragma unroll
            for (int j = 0; j < 4; j++) {
                uint32_t b0 = __float_as_uint(Ks[(j * 8 + gr) * KSTW + k0 + tg]);
                uint32_t b1 = __float_as_uint(Ks[(j * 8 + gr) * KSTW + k0 + 4 + tg]);
                mma_tf32(sacc[j], qf[ks], b0, b1);
            }
        }

        // causal mask + row max
        float tm0 = -CUDART_INF_F, tm1 = -CUDART_INF_F;
#pragma unroll
        for (int j = 0; j < 4; j++) {
            int kcol = kb + j * 8 + 2 * tg;
            if (kcol     > t0) sacc[j][0] = -CUDART_INF_F;
            if (kcol + 1 > t0) sacc[j][1] = -CUDART_INF_F;
            if (kcol     > t1) sacc[j][2] = -CUDART_INF_F;
            if (kcol + 1 > t1) sacc[j][3] = -CUDART_INF_F;
            tm0 = fmaxf(tm0, fmaxf(sacc[j][0], sacc[j][1]));
            tm1 = fmaxf(tm1, fmaxf(sacc[j][2], sacc[j][3]));
        }
        tm0 = fmaxf(tm0, __shfl_xor_sync(0xffffffffu, tm0, 1));
        tm0 = fmaxf(tm0, __shfl_xor_sync(0xffffffffu, tm0, 2));
        tm1 = fmaxf(tm1, __shfl_xor_sync(0xffffffffu, tm1, 1));
        tm1 = fmaxf(tm1, __shfl_xor_sync(0xffffffffu, tm1, 2));

        float mn0 = fmaxf(m0, tm0);
        float mn1 = fmaxf(m1, tm1);
        float c0 = __expf(m0 - mn0);
        float c1 = __expf(m1 - mn1);

        float ps0 = 0.f, ps1 = 0.f;
#pragma unroll
        for (int j = 0; j < 4; j++) {
            uint32_t p0 = f2tf32(__expf(sacc[j][0] - mn0));
            uint32_t p1 = f2tf32(__expf(sacc[j][1] - mn0));
            uint32_t p2 = f2tf32(__expf(sacc[j][2] - mn1));
            uint32_t p3 = f2tf32(__expf(sacc[j][3] - mn1));
            ps0 += __uint_as_float(p0) + __uint_as_float(p1);
            ps1 += __uint_as_float(p2) + __uint_as_float(p3);
            uint2 w0 = { p0, p1 };
            uint2 w1 = { p2, p3 };
            *(uint2*)(Ps + (wm + gr) * PST + j * 8 + 2 * tg)     = w0;
            *(uint2*)(Ps + (wm + 8 + gr) * PST + j * 8 + 2 * tg) = w1;
        }
        ps0 += __shfl_xor_sync(0xffffffffu, ps0, 1);
        ps0 += __shfl_xor_sync(0xffffffffu, ps0, 2);
        ps1 += __shfl_xor_sync(0xffffffffu, ps1, 1);
        ps1 += __shfl_xor_sync(0xffffffffu, ps1, 2);

        l0 = l0 * c0 + ps0;
        l1 = l1 * c1 + ps1;
        m0 = mn0; m1 = mn1;

#pragma unroll
        for (int f = 0; f < 16; f++) {
            oacc[f][0] *= c0; oacc[f][1] *= c0;
            oacc[f][2] *= c1; oacc[f][3] *= c1;
        }
        __syncwarp();   // P writes visible within warp

        // O += P @ V
#pragma unroll
        for (int ks2 = 0; ks2 < 4; ks2++) {
            int k0 = ks2 * 8;
            uint32_t a[4];
            a[0] = __float_as_uint(Ps[(wm + gr) * PST + k0 + tg]);
            a[1] = __float_as_uint(Ps[(wm + 8 + gr) * PST + k0 + tg]);
            a[2] = __float_as_uint(Ps[(wm + gr) * PST + k0 + 4 + tg]);
            a[3] = __float_as_uint(Ps[(wm + 8 + gr) * PST + k0 + 4 + tg]);
#pragma unroll
            for (int f = 0; f < 16; f++) {
                uint32_t b0 = __float_as_uint(Vs[(k0 + tg) * VSTW + f * 8 + gr]);
                uint32_t b1 = __float_as_uint(Vs[(k0 + 4 + tg) * VSTW + f * 8 + gr]);
                mma_tf32(oacc[f], a, b0, b1);
            }
        }
        __syncthreads();   // all warps done with this stage before overwrite
    }

    float inv0 = 1.0f / l0;
    float inv1 = 1.0f / l1;
    float* o0 = O + ((size_t)t0 * HQ + h) * HD;
    float* o1 = O + ((size_t)t1 * HQ + h) * HD;
#pragma unroll
    for (int f = 0; f < 16; f++) {
        int cc = f * 8 + 2 * tg;
        float2 v0 = { oacc[f][0] * inv0, oacc[f][1] * inv0 };
        float2 v1 = { oacc[f][2] * inv1, oacc[f][3] * inv1 };
        *(float2*)(o0 + cc) = v0;
        *(float2*)(o1 + cc) = v1;
    }
}

// ---------------------------------------------------------------------------
// Launch
// ---------------------------------------------------------------------------
static void launch_round(const float* in, float* out, size_t n) {
    int n4 = (int)(n / 4);
    round_kernel<<<(n4 + 255) / 256, 256>>>(in, out, n4);
}

extern "C" void kernel_launch(void* const* d_in, const int* in_sizes, int n_in,
                              void* d_out, int out_size)
{
    const float* x   = (const float*)d_in[0];
    const float* cs  = (const float*)d_in[1];
    const float* sn  = (const float*)d_in[2];
    const float* wq  = (const float*)d_in[3];
    const float* wk  = (const float*)d_in[4];
    const float* wv  = (const float*)d_in[5];
    const float* wo  = (const float*)d_in[6];
    float* out = (float*)d_out;

    float *pq, *pk, *pv, *patt, *pxr, *pwqr, *pwkr, *pwvr, *pwor;
    cudaGetSymbolAddress((void**)&pq,   g_q);
    cudaGetSymbolAddress((void**)&pk,   g_k);
    cudaGetSymbolAddress((void**)&pv,   g_v);
    cudaGetSymbolAddress((void**)&patt, g_att);
    cudaGetSymbolAddress((void**)&pxr,  g_xr);
    cudaGetSymbolAddress((void**)&pwqr, g_wqr);
    cudaGetSymbolAddress((void**)&pwkr, g_wkr);
    cudaGetSymbolAddress((void**)&pwvr, g_wvr);
    cudaGetSymbolAddress((void**)&pwor, g_wor);

    cudaFuncSetAttribute(gemm_async, cudaFuncAttributeMaxDynamicSharedMemorySize,
                         GEMM_SMEM);
    cudaFuncSetAttribute(flash_async, cudaFuncAttributeMaxDynamicSharedMemorySize,
                         FLASH_SMEM);

    // tf32 pre-rounding (mma then consumes raw bits exactly)
    launch_round(x,  pxr,  (size_t)T_SEQ * C_EMB);
    launch_round(wq, pwqr, (size_t)C_EMB * C_EMB);
    launch_round(wk, pwkr, (size_t)C_EMB * KVD);
    launch_round(wv, pwvr, (size_t)C_EMB * KVD);
    launch_round(wo, pwor, (size_t)C_EMB * C_EMB);

    // QKV projections
    gemm_async<<<dim3(C_EMB / BN, T_SEQ / BM), 256, GEMM_SMEM>>>(
        pxr, pwqr, pq, T_SEQ, C_EMB, C_EMB);
    gemm_async<<<dim3(KVD / BN, T_SEQ / BM), 256, GEMM_SMEM>>>(
        pxr, pwkr, pk, T_SEQ, KVD, C_EMB);
    gemm_async<<<dim3(KVD / BN, T_SEQ / BM), 256, GEMM_SMEM>>>(
        pxr, pwvr, pv, T_SEQ, KVD, C_EMB);

    // RoPE + RMSNorm (K output pre-rounded for flash's cp.async path)
    rope_rms_kernel<<<dim3(T_SEQ, HQ),  64>>>(pq, cs, sn, HQ, 0);
    rope_rms_kernel<<<dim3(T_SEQ, HKV), 64>>>(pk, cs, sn, HKV, 1);
    launch_round(pv, pv, (size_t)T_SEQ * KVD);   // V pre-round in place

    // Flash attention
    flash_async<<<dim3(T_SEQ / FBQ, HQ), 128, FLASH_SMEM>>>(pq, pk, pv, patt);

    // Output projection
    launch_round(patt, patt, (size_t)T_SEQ * C_EMB);
    gemm_async<<<dim3(C_EMB / BN, T_SEQ / BM), 256, GEMM_SMEM>>>(
        patt, pwor, out, T_SEQ, C_EMB, C_EMB);
}